// round 2
// baseline (speedup 1.0000x reference)
#include <cuda_runtime.h>

#define B_   16
#define C_   512
#define N_   1681
#define CK_  256
#define NT_  27          // ceil(1681/64)
#define SCALE_ 0.0625f   // 1/sqrt(256)
#define EPS_  1e-5f

// ---- scratch (device globals; no allocation allowed) ----
__device__ float g_Q[B_ * N_ * CK_];                 // [b, n, k]
__device__ float g_K[B_ * N_ * CK_];                 // [b, m, k]
__device__ float g_S[(size_t)B_ * N_ * N_];          // sim1 = qk*scale*fg, [b, n, m]
__device__ float g_pss[B_ * NT_ * N_];               // partial sum sim1*fg per m-tile
__device__ float g_pfs[B_ * NT_ * N_];               // partial sum fg per m-tile
__device__ float g_pmin[B_ * NT_ * N_];              // partial min sim1 per m-tile
__device__ float g_inv[B_ * N_];                     // 1/(D+eps)
__device__ float g_minv[B_ * N_];                    // row min

// ============================================================
// Kernel 1: projections  O[b,n,k] = sum_c x[b,c,n]*W[k,c] + bias[k]
// grid: (27 n-tiles, 4 k-tiles, 32 = b*2 + {Q,K}); block 256
// ============================================================
__global__ __launch_bounds__(256)
void proj_kernel(const float* __restrict__ x,
                 const float* __restrict__ Wq, const float* __restrict__ bq,
                 const float* __restrict__ Wk, const float* __restrict__ bk)
{
    int bz  = blockIdx.z;
    int b   = bz >> 1;
    int isK = bz & 1;
    const float* W    = isK ? Wk : Wq;
    const float* bias = isK ? bk : bq;
    float*       O    = isK ? g_K : g_Q;

    int n0 = blockIdx.x * 64;
    int k0 = blockIdx.y * 64;

    __shared__ __align__(16) float As[16][68];  // As[cc][nn] = x[b, c0+cc, n0+nn]
    __shared__ __align__(16) float Bs[16][68];  // Bs[cc][kk] = W[k0+kk, c0+cc]

    int t  = threadIdx.x;
    int tx = t & 15, ty = t >> 4;
    float acc[4][4] = {};
    const float* xb = x + (size_t)b * C_ * N_;

    for (int c0 = 0; c0 < C_; c0 += 16) {
        {   // load x tile, coalesced over n
            int nn  = t & 63;
            int cc0 = t >> 6;
            int n   = n0 + nn;
            #pragma unroll
            for (int r = 0; r < 4; r++) {
                int cc = cc0 + r * 4;
                As[cc][nn] = (n < N_) ? xb[(size_t)(c0 + cc) * N_ + n] : 0.f;
            }
        }
        {   // load W tile, coalesced over c
            int cc  = t & 15;
            int kk0 = t >> 4;
            #pragma unroll
            for (int r = 0; r < 4; r++) {
                int kk = kk0 + r * 16;
                Bs[cc][kk] = W[(size_t)(k0 + kk) * C_ + c0 + cc];
            }
        }
        __syncthreads();
        #pragma unroll
        for (int cc = 0; cc < 16; cc++) {
            float4 a4 = *(const float4*)&As[cc][ty * 4];
            float4 b4 = *(const float4*)&Bs[cc][tx * 4];
            float a[4] = {a4.x, a4.y, a4.z, a4.w};
            float bb[4] = {b4.x, b4.y, b4.z, b4.w};
            #pragma unroll
            for (int i = 0; i < 4; i++)
                #pragma unroll
                for (int j = 0; j < 4; j++)
                    acc[i][j] += a[i] * bb[j];
        }
        __syncthreads();
    }
    #pragma unroll
    for (int i = 0; i < 4; i++) {
        int n = n0 + ty * 4 + i;
        if (n < N_) {
            #pragma unroll
            for (int j = 0; j < 4; j++) {
                int k = k0 + tx * 4 + j;
                O[((size_t)b * N_ + n) * CK_ + k] = acc[i][j] + bias[k];
            }
        }
    }
}

// ============================================================
// Kernel 2: sim1[b,n,m] = (Q[b,n,:] . K[b,m,:]) * scale * fg[b,n,m]
// + per-(m-tile) row partials: min(sim1), sum(sim1*fg), sum(fg)
// grid: (27 m-tiles, 27 n-tiles, 16 b); block 256
// ============================================================
__global__ __launch_bounds__(256)
void sim_kernel(const float* __restrict__ fg)
{
    int b  = blockIdx.z;
    int n0 = blockIdx.y * 64;
    int m0 = blockIdx.x * 64;

    __shared__ __align__(16) float As[16][68];  // As[kk][nn]
    __shared__ __align__(16) float Bs[16][68];  // Bs[kk][mm]

    int t  = threadIdx.x;
    int tx = t & 15, ty = t >> 4;
    float acc[4][4] = {};
    const float* Qb = g_Q + (size_t)b * N_ * CK_;
    const float* Kb = g_K + (size_t)b * N_ * CK_;

    for (int k0 = 0; k0 < CK_; k0 += 16) {
        {
            int col  = t & 15;
            int row0 = t >> 4;
            #pragma unroll
            for (int r = 0; r < 4; r++) {
                int row = row0 + r * 16;
                int n = n0 + row;
                As[col][row] = (n < N_) ? Qb[(size_t)n * CK_ + k0 + col] : 0.f;
                int m = m0 + row;
                Bs[col][row] = (m < N_) ? Kb[(size_t)m * CK_ + k0 + col] : 0.f;
            }
        }
        __syncthreads();
        #pragma unroll
        for (int kk = 0; kk < 16; kk++) {
            float4 a4 = *(const float4*)&As[kk][ty * 4];
            float4 b4 = *(const float4*)&Bs[kk][tx * 4];
            float a[4] = {a4.x, a4.y, a4.z, a4.w};
            float bb[4] = {b4.x, b4.y, b4.z, b4.w};
            #pragma unroll
            for (int i = 0; i < 4; i++)
                #pragma unroll
                for (int j = 0; j < 4; j++)
                    acc[i][j] += a[i] * bb[j];
        }
        __syncthreads();
    }

    // epilogue: apply scale*fg, store sim1, compute row partials
    const float* fgb = fg + (size_t)b * N_ * N_;
    float*       Sb  = g_S + (size_t)b * N_ * N_;
    float rmin[4], rss[4], rfs[4];
    #pragma unroll
    for (int i = 0; i < 4; i++) { rmin[i] = 3.4e38f; rss[i] = 0.f; rfs[i] = 0.f; }

    #pragma unroll
    for (int i = 0; i < 4; i++) {
        int n = n0 + ty * 4 + i;
        if (n < N_) {
            #pragma unroll
            for (int j = 0; j < 4; j++) {
                int m = m0 + tx * 4 + j;
                if (m < N_) {
                    size_t off = (size_t)n * N_ + m;
                    float f  = fgb[off];
                    float s1 = acc[i][j] * SCALE_ * f;
                    Sb[off]  = s1;
                    rmin[i]  = fminf(rmin[i], s1);
                    rss[i]  += s1 * f;
                    rfs[i]  += f;
                }
            }
        }
    }
    // reduce across 16 threads sharing the same rows (contiguous 16-lane group)
    #pragma unroll
    for (int i = 0; i < 4; i++) {
        #pragma unroll
        for (int off = 8; off > 0; off >>= 1) {
            rmin[i] = fminf(rmin[i], __shfl_down_sync(0xFFFFFFFFu, rmin[i], off, 16));
            rss[i] += __shfl_down_sync(0xFFFFFFFFu, rss[i], off, 16);
            rfs[i] += __shfl_down_sync(0xFFFFFFFFu, rfs[i], off, 16);
        }
        if (tx == 0) {
            int n = n0 + ty * 4 + i;
            if (n < N_) {
                size_t idx = ((size_t)b * NT_ + blockIdx.x) * N_ + n;
                g_pmin[idx] = rmin[i];
                g_pss[idx]  = rss[i];
                g_pfs[idx]  = rfs[i];
            }
        }
    }
}

// ============================================================
// Kernel 3: finalize per-row stats
// ============================================================
__global__ __launch_bounds__(256)
void fin_stats()
{
    int i = blockIdx.x * blockDim.x + threadIdx.x;
    if (i >= B_ * N_) return;
    int b = i / N_;
    int n = i - b * N_;
    float mn = 3.4e38f, ss = 0.f, fs = 0.f;
    #pragma unroll 1
    for (int tile = 0; tile < NT_; tile++) {
        size_t idx = ((size_t)b * NT_ + tile) * N_ + n;
        mn = fminf(mn, g_pmin[idx]);
        ss += g_pss[idx];
        fs += g_pfs[idx];
    }
    float D = ss - mn * fs;
    g_inv[i]  = 1.f / (D + EPS_);
    g_minv[i] = mn;
}

// ============================================================
// Kernel 4: context GEMM with on-the-fly A-transform + fuse epilogue
// A[n,m] = (sim1 - min_n)*fg*inv_n + bg ; ctx = A @ V, V[m,c] = x[b,c,m]
// out[b,c,n] = gamma*ctx[n,c] + x[b,c,n]
// grid: (27 n-tiles, 8 c-tiles, 16 b); block 256
// ============================================================
__global__ __launch_bounds__(256)
void ctx_kernel(const float* __restrict__ x,
                const float* __restrict__ fg,
                const float* __restrict__ bg,
                const float* __restrict__ gamma,
                float* __restrict__ out)
{
    int b  = blockIdx.z;
    int n0 = blockIdx.x * 64;
    int c0 = blockIdx.y * 64;

    __shared__ __align__(16) float As[16][68];  // As[mm][nn] (transformed A)
    __shared__ __align__(16) float Bs[16][68];  // Bs[mm][cc] (V)
    __shared__ float s_inv[64], s_minv[64];

    int t  = threadIdx.x;
    int tx = t & 15, ty = t >> 4;

    if (t < 64) {
        int n = n0 + t;
        s_inv[t]  = (n < N_) ? g_inv[b * N_ + n]  : 0.f;
        s_minv[t] = (n < N_) ? g_minv[b * N_ + n] : 0.f;
    }
    __syncthreads();

    float acc[4][4] = {};
    const float* xb  = x  + (size_t)b * C_ * N_;
    const float* Sb  = g_S + (size_t)b * N_ * N_;
    const float* fgb = fg + (size_t)b * N_ * N_;
    const float* bgb = bg + (size_t)b * N_ * N_;

    for (int m0 = 0; m0 < N_; m0 += 16) {
        int mm = t & 15;
        int m  = m0 + mm;
        {   // A tile (coalesced over m)
            int nn0 = t >> 4;
            #pragma unroll
            for (int r = 0; r < 4; r++) {
                int nn = nn0 + r * 16;
                int n  = n0 + nn;
                float a = 0.f;
                if (n < N_ && m < N_) {
                    size_t off = (size_t)n * N_ + m;
                    float s1 = Sb[off];
                    float f  = fgb[off];
                    float g  = bgb[off];
                    a = (s1 - s_minv[nn]) * f * s_inv[nn] + g;
                }
                As[mm][nn] = a;
            }
        }
        {   // V tile (coalesced over m)
            int cc0 = t >> 4;
            #pragma unroll
            for (int r = 0; r < 4; r++) {
                int cc = cc0 + r * 16;
                Bs[mm][cc] = (m < N_) ? xb[(size_t)(c0 + cc) * N_ + m] : 0.f;
            }
        }
        __syncthreads();
        #pragma unroll
        for (int k = 0; k < 16; k++) {
            float4 a4 = *(const float4*)&As[k][ty * 4];
            float4 b4 = *(const float4*)&Bs[k][tx * 4];
            float a[4] = {a4.x, a4.y, a4.z, a4.w};
            float bb[4] = {b4.x, b4.y, b4.z, b4.w};
            #pragma unroll
            for (int i = 0; i < 4; i++)
                #pragma unroll
                for (int j = 0; j < 4; j++)
                    acc[i][j] += a[i] * bb[j];
        }
        __syncthreads();
    }

    float gam = gamma[0];
    #pragma unroll
    for (int i = 0; i < 4; i++) {
        int n = n0 + ty * 4 + i;
        if (n < N_) {
            #pragma unroll
            for (int j = 0; j < 4; j++) {
                int c = c0 + tx * 4 + j;
                size_t o = (size_t)b * C_ * N_ + (size_t)c * N_ + n;
                out[o] = gam * acc[i][j] + x[o];
            }
        }
    }
}

// ============================================================
extern "C" void kernel_launch(void* const* d_in, const int* in_sizes, int n_in,
                              void* d_out, int out_size)
{
    const float* x     = (const float*)d_in[0];
    const float* fg    = (const float*)d_in[1];
    const float* bg    = (const float*)d_in[2];
    const float* Wq    = (const float*)d_in[3];
    const float* bq    = (const float*)d_in[4];
    const float* Wk    = (const float*)d_in[5];
    const float* bk    = (const float*)d_in[6];
    const float* gamma = (const float*)d_in[7];
    float* out = (float*)d_out;

    dim3 gp(NT_, CK_ / 64, B_ * 2);
    proj_kernel<<<gp, 256>>>(x, Wq, bq, Wk, bk);

    dim3 gs(NT_, NT_, B_);
    sim_kernel<<<gs, 256>>>(fg);

    fin_stats<<<(B_ * N_ + 255) / 256, 256>>>();

    dim3 gc(NT_, C_ / 64, B_);
    ctx_kernel<<<gc, 256>>>(x, fg, bg, gamma, out);
}

// round 4
// speedup vs baseline: 2.3607x; 2.3607x over previous
#include <cuda_runtime.h>
#include <cuda_bf16.h>

#define B_    16
#define C_    512
#define N_    1681
#define CK_   256
#define MPQ_  1792          // Q/K n-padding (14*128)
#define MP2_  1728          // attention m-padding (54*32)
#define NTT_  14
#define SCALE_ 0.0625f
#define EPS_  1e-5f

// ---------------- device scratch ----------------
__device__ __nv_bfloat16 g_Qhi[(size_t)B_*CK_*MPQ_], g_Qlo[(size_t)B_*CK_*MPQ_];
__device__ __nv_bfloat16 g_Khi[(size_t)B_*CK_*MPQ_], g_Klo[(size_t)B_*CK_*MPQ_];
__device__ float g_S[(size_t)B_*N_*MP2_];
__device__ __nv_bfloat16 g_AHi[(size_t)B_*N_*MP2_], g_ALo[(size_t)B_*N_*MP2_];
__device__ float g_pmin[B_*NTT_*N_], g_pss[B_*NTT_*N_], g_pfs[B_*NTT_*N_];
__device__ float g_inv[B_*N_], g_minv[B_*N_];

// ---------------- helpers ----------------
__device__ __forceinline__ unsigned s2u(const void* p) {
    unsigned a;
    asm("{ .reg .u64 t; cvta.to.shared.u64 t, %1; cvt.u32.u64 %0, t; }" : "=r"(a) : "l"(p));
    return a;
}
__device__ __forceinline__ void ldsm4(unsigned* r, unsigned a) {
    asm volatile("ldmatrix.sync.aligned.m8n8.x4.shared.b16 {%0,%1,%2,%3}, [%4];"
                 : "=r"(r[0]), "=r"(r[1]), "=r"(r[2]), "=r"(r[3]) : "r"(a));
}
__device__ __forceinline__ void ldsm4t(unsigned* r, unsigned a) {
    asm volatile("ldmatrix.sync.aligned.m8n8.x4.trans.shared.b16 {%0,%1,%2,%3}, [%4];"
                 : "=r"(r[0]), "=r"(r[1]), "=r"(r[2]), "=r"(r[3]) : "r"(a));
}
__device__ __forceinline__ void mma_bf(float* c, const unsigned* a, unsigned b0, unsigned b1) {
    asm volatile("mma.sync.aligned.m16n8k16.row.col.f32.bf16.bf16.f32 "
                 "{%0,%1,%2,%3}, {%4,%5,%6,%7}, {%8,%9}, {%0,%1,%2,%3};"
                 : "+f"(c[0]), "+f"(c[1]), "+f"(c[2]), "+f"(c[3])
                 : "r"(a[0]), "r"(a[1]), "r"(a[2]), "r"(a[3]), "r"(b0), "r"(b1));
}
// direct tile: [row128][kd32] bf16, row stride 80B. trans tile: [kd32][col128] bf16, stride 272B.
__device__ __forceinline__ void ldA_dir(unsigned* a, unsigned tb, int mb, int ks, int L) {
    int q = L >> 3, rs = L & 7;
    ldsm4(a, tb + (unsigned)((mb + (q & 1) * 8 + rs) * 80 + (ks * 2 + (q >> 1)) * 16));
}
__device__ __forceinline__ void ldA_trn(unsigned* a, unsigned tb, int mb, int ks, int L) {
    int q = L >> 3, rs = L & 7;
    ldsm4t(a, tb + (unsigned)((ks * 16 + (q >> 1) * 8 + rs) * 272 + (mb + (q & 1) * 8) * 2));
}
__device__ __forceinline__ void ldB_dir(unsigned* b, unsigned tb, int nb, int ks, int L) {
    int q = L >> 3, rs = L & 7;
    ldsm4(b, tb + (unsigned)((nb + (q >> 1) * 8 + rs) * 80 + (ks * 2 + (q & 1)) * 16));
}
__device__ __forceinline__ void ldB_trn(unsigned* b, unsigned tb, int nb, int ks, int L) {
    int q = L >> 3, rs = L & 7;
    ldsm4t(b, tb + (unsigned)((ks * 16 + (q & 1) * 8 + rs) * 272 + (nb + (q >> 1) * 8) * 2));
}
__device__ __forceinline__ void split_pack(float a0, float a1, unsigned& hi, unsigned& lo) {
    __nv_bfloat162 h, l;
    h.x = __float2bfloat16_rn(a0); h.y = __float2bfloat16_rn(a1);
    l.x = __float2bfloat16_rn(a0 - __bfloat162float(h.x));
    l.y = __float2bfloat16_rn(a1 - __bfloat162float(h.y));
    hi = *(unsigned*)&h; lo = *(unsigned*)&l;
}

template<int AT, int BT>
__device__ __forceinline__ void gemm_chunk(float (*acc)[4][4], unsigned ah, unsigned al,
                                           unsigned bh, unsigned bl, int wm, int wn, int L)
{
    #pragma unroll
    for (int ks = 0; ks < 2; ks++) {
        unsigned aH[16], aL[16], bH[8], bL[8];
        #pragma unroll
        for (int fm = 0; fm < 4; fm++) {
            int mb = wm * 64 + fm * 16;
            if (AT) { ldA_trn(aH + fm*4, ah, mb, ks, L); ldA_trn(aL + fm*4, al, mb, ks, L); }
            else    { ldA_dir(aH + fm*4, ah, mb, ks, L); ldA_dir(aL + fm*4, al, mb, ks, L); }
        }
        #pragma unroll
        for (int fp = 0; fp < 2; fp++) {
            int nb = wn * 32 + fp * 16;
            if (BT) { ldB_trn(bH + fp*4, bh, nb, ks, L); ldB_trn(bL + fp*4, bl, nb, ks, L); }
            else    { ldB_dir(bH + fp*4, bh, nb, ks, L); ldB_dir(bL + fp*4, bl, nb, ks, L); }
        }
        #pragma unroll
        for (int fm = 0; fm < 4; fm++)
            #pragma unroll
            for (int fn = 0; fn < 4; fn++) {
                int bi = (fn >> 1) * 4 + (fn & 1) * 2;
                mma_bf(acc[fm][fn], aH + fm*4, bH[bi], bH[bi+1]);
                mma_bf(acc[fm][fn], aH + fm*4, bL[bi], bL[bi+1]);
                mma_bf(acc[fm][fn], aL + fm*4, bH[bi], bH[bi+1]);
            }
    }
}

// ============ proj: D[k,n] = W@x + b, store split [b][k][n-pad] ============
__global__ __launch_bounds__(256)
void proj_t(const float* __restrict__ x,
            const float* __restrict__ Wq, const float* __restrict__ bq,
            const float* __restrict__ Wk, const float* __restrict__ bk)
{
    __shared__ __align__(16) char sm[20480 + 17408];
    unsigned sA = s2u(sm), sAl = sA + 10240, sB = sA + 20480, sBl = sB + 8704;
    int t = threadIdx.x, L = t & 31, w = t >> 5, wm = w & 1, wn = w >> 1;
    int z = blockIdx.z, b = z >> 1, isK = z & 1;
    const float* W    = isK ? Wk : Wq;
    const float* bias = isK ? bk : bq;
    __nv_bfloat16* Ohi = isK ? g_Khi : g_Qhi;
    __nv_bfloat16* Olo = isK ? g_Klo : g_Qlo;
    int n0 = blockIdx.x * 128, k0 = blockIdx.y * 128;

    float acc[4][4][4] = {};
    for (int c0 = 0; c0 < C_; c0 += 32) {
        {   // A = W rows k (coalesced float4)
            int r = t >> 1, hf = t & 1;
            const float4* Wp = (const float4*)(W + (size_t)(k0 + r) * C_ + c0 + hf * 16);
            unsigned hi[8], lo[8];
            #pragma unroll
            for (int v = 0; v < 4; v++) {
                float4 f = Wp[v];
                split_pack(f.x, f.y, hi[2*v], lo[2*v]);
                split_pack(f.z, f.w, hi[2*v+1], lo[2*v+1]);
            }
            unsigned off = r * 80 + hf * 32;
            *(uint4*)(sm + off)              = ((uint4*)hi)[0];
            *(uint4*)(sm + off + 16)         = ((uint4*)hi)[1];
            *(uint4*)(sm + 10240 + off)      = ((uint4*)lo)[0];
            *(uint4*)(sm + 10240 + off + 16) = ((uint4*)lo)[1];
        }
        {   // B = x rows c (n contiguous), trans layout
            int r = t >> 3, seg = t & 7;
            const float* xp = x + ((size_t)b * C_ + c0 + r) * N_ + n0 + seg * 16;
            int nb = n0 + seg * 16;
            unsigned hi[8], lo[8];
            #pragma unroll
            for (int j = 0; j < 8; j++) {
                int n1 = nb + 2*j;
                float f0 = (n1     < N_) ? __ldg(xp + 2*j)     : 0.f;
                float f1 = (n1 + 1 < N_) ? __ldg(xp + 2*j + 1) : 0.f;
                split_pack(f0, f1, hi[j], lo[j]);
            }
            unsigned off = 20480 + r * 272 + seg * 32;
            *(uint4*)(sm + off)             = ((uint4*)hi)[0];
            *(uint4*)(sm + off + 16)        = ((uint4*)hi)[1];
            *(uint4*)(sm + 8704 + off)      = ((uint4*)lo)[0];
            *(uint4*)(sm + 8704 + off + 16) = ((uint4*)lo)[1];
        }
        __syncthreads();
        gemm_chunk<0, 1>(acc, sA, sAl, sB, sBl, wm, wn, L);
        __syncthreads();
    }
    #pragma unroll
    for (int fm = 0; fm < 4; fm++) {
        #pragma unroll
        for (int rh = 0; rh < 2; rh++) {
            int k = k0 + wm * 64 + fm * 16 + (L >> 2) + rh * 8;
            float bia = bias[k];
            #pragma unroll
            for (int fn = 0; fn < 4; fn++) {
                int n = n0 + wn * 32 + fn * 8 + 2 * (L & 3);
                float v0 = acc[fm][fn][rh*2]   + bia;
                float v1 = acc[fm][fn][rh*2+1] + bia;
                unsigned hp, lp;
                split_pack(v0, v1, hp, lp);
                size_t idx = ((size_t)b * CK_ + k) * MPQ_ + n;
                *(unsigned*)(Ohi + idx) = hp;
                *(unsigned*)(Olo + idx) = lp;
            }
        }
    }
}

// ============ sim: S[n,m] = (Q.K^T)*scale*fg + row stats ============
__global__ __launch_bounds__(256)
void sim_t(const float* __restrict__ fg)
{
    __shared__ __align__(16) char sm[34816 + 6144];
    unsigned sQ = s2u(sm), sQl = sQ + 8704, sK = sQ + 17408, sKl = sQ + 26112;
    float* red = (float*)(sm + 34816);     // [3][8][64]
    int t = threadIdx.x, L = t & 31, w = t >> 5, wm = w & 1, wn = w >> 1;
    int b = blockIdx.z, m0 = blockIdx.x * 128, n0 = blockIdx.y * 128;

    float acc[4][4][4] = {};
    for (int k0 = 0; k0 < CK_; k0 += 32) {
        int r = t >> 3, seg = t & 7;
        size_t qi = ((size_t)b * CK_ + k0 + r) * MPQ_ + n0 + seg * 16;
        size_t ki = ((size_t)b * CK_ + k0 + r) * MPQ_ + m0 + seg * 16;
        unsigned off = r * 272 + seg * 32;
        *(uint4*)(sm + off)              = *(const uint4*)(g_Qhi + qi);
        *(uint4*)(sm + off + 16)         = *(const uint4*)(g_Qhi + qi + 8);
        *(uint4*)(sm + 8704  + off)      = *(const uint4*)(g_Qlo + qi);
        *(uint4*)(sm + 8704  + off + 16) = *(const uint4*)(g_Qlo + qi + 8);
        *(uint4*)(sm + 17408 + off)      = *(const uint4*)(g_Khi + ki);
        *(uint4*)(sm + 17408 + off + 16) = *(const uint4*)(g_Khi + ki + 8);
        *(uint4*)(sm + 26112 + off)      = *(const uint4*)(g_Klo + ki);
        *(uint4*)(sm + 26112 + off + 16) = *(const uint4*)(g_Klo + ki + 8);
        __syncthreads();
        gemm_chunk<1, 1>(acc, sQ, sQl, sK, sKl, wm, wn, L);
        __syncthreads();
    }

    float rmn[4][2], rss[4][2], rfs[4][2];
    #pragma unroll
    for (int fm = 0; fm < 4; fm++)
        #pragma unroll
        for (int rh = 0; rh < 2; rh++) { rmn[fm][rh] = 3.4e38f; rss[fm][rh] = 0.f; rfs[fm][rh] = 0.f; }

    #pragma unroll
    for (int fm = 0; fm < 4; fm++)
        #pragma unroll
        for (int rh = 0; rh < 2; rh++) {
            int n = n0 + wm * 64 + fm * 16 + (L >> 2) + rh * 8;
            if (n < N_) {
                size_t fb = (size_t)b * N_ * N_ + (size_t)n * N_;
                size_t sb = (size_t)b * N_ * MP2_ + (size_t)n * MP2_;
                #pragma unroll
                for (int fn = 0; fn < 4; fn++)
                    #pragma unroll
                    for (int e = 0; e < 2; e++) {
                        int m = m0 + wn * 32 + fn * 8 + 2 * (L & 3) + e;
                        if (m < N_) {
                            float f = __ldg(fg + fb + m);
                            float s1 = acc[fm][fn][rh*2 + e] * SCALE_ * f;
                            g_S[sb + m] = s1;
                            rmn[fm][rh] = fminf(rmn[fm][rh], s1);
                            rss[fm][rh] += s1 * f;
                            rfs[fm][rh] += f;
                        }
                    }
            }
        }
    #pragma unroll
    for (int fm = 0; fm < 4; fm++)
        #pragma unroll
        for (int rh = 0; rh < 2; rh++) {
            #pragma unroll
            for (int xr = 1; xr < 4; xr <<= 1) {
                rmn[fm][rh] = fminf(rmn[fm][rh], __shfl_xor_sync(0xFFFFFFFFu, rmn[fm][rh], xr));
                rss[fm][rh] += __shfl_xor_sync(0xFFFFFFFFu, rss[fm][rh], xr);
                rfs[fm][rh] += __shfl_xor_sync(0xFFFFFFFFu, rfs[fm][rh], xr);
            }
            if ((L & 3) == 0) {
                int ri = w * 64 + fm * 16 + rh * 8 + (L >> 2);
                red[ri] = rmn[fm][rh];
                red[512 + ri] = rss[fm][rh];
                red[1024 + ri] = rfs[fm][rh];
            }
        }
    __syncthreads();
    if (t < 128) {
        int hf = t >> 6, row = t & 63;
        float mn = 3.4e38f, ss = 0.f, fs = 0.f;
        #pragma unroll
        for (int j = 0; j < 4; j++) {
            int ww = hf + 2 * j;
            mn = fminf(mn, red[ww * 64 + row]);
            ss += red[512 + ww * 64 + row];
            fs += red[1024 + ww * 64 + row];
        }
        int n = n0 + hf * 64 + row;
        if (n < N_) {
            size_t idx = ((size_t)b * NTT_ + blockIdx.x) * N_ + n;
            g_pmin[idx] = mn; g_pss[idx] = ss; g_pfs[idx] = fs;
        }
    }
}

// ============ fin_stats ============
__global__ __launch_bounds__(256)
void fin_stats()
{
    int i = blockIdx.x * blockDim.x + threadIdx.x;
    if (i >= B_ * N_) return;
    int b = i / N_, n = i - b * N_;
    float mn = 3.4e38f, ss = 0.f, fs = 0.f;
    #pragma unroll 1
    for (int tile = 0; tile < NTT_; tile++) {
        size_t idx = ((size_t)b * NTT_ + tile) * N_ + n;
        mn = fminf(mn, g_pmin[idx]);
        ss += g_pss[idx];
        fs += g_pfs[idx];
    }
    g_inv[i] = 1.f / ((ss - mn * fs) + EPS_);
    g_minv[i] = mn;
}

// ============ xform: attn = (S-min)*fg*inv + bg, split bf16, zero-pad ============
__global__ __launch_bounds__(256)
void xform(const float* __restrict__ fg, const float* __restrict__ bg)
{
    int r = blockIdx.x;               // b*N_ + n
    float mn = g_minv[r], iv = g_inv[r];
    size_t sbase = (size_t)r * MP2_;
    size_t fbase = (size_t)r * N_ + ((size_t)(r / N_)) * ((size_t)N_ * N_ - (size_t)N_ * N_);
    // fg/bg base: (b*N_+n)*N_ == r*N_
    size_t gbase = (size_t)r * N_;
    for (int m = threadIdx.x; m < MP2_; m += 256) {
        float a = 0.f;
        if (m < N_) {
            float s1 = g_S[sbase + m];
            float f  = __ldg(fg + gbase + m);
            float g  = __ldg(bg + gbase + m);
            a = (s1 - mn) * f * iv + g;
        }
        __nv_bfloat16 h = __float2bfloat16_rn(a);
        g_AHi[sbase + m] = h;
        g_ALo[sbase + m] = __float2bfloat16_rn(a - __bfloat162float(h));
    }
    (void)fbase;
}

// ============ ctx: out[c,n] = gamma*(attn @ x^T)[n,c] + x[c,n] ============
__global__ __launch_bounds__(256)
void ctx_t(const float* __restrict__ x, const float* __restrict__ gamma,
           float* __restrict__ out)
{
    __shared__ __align__(16) char sm[40960];
    unsigned sA = s2u(sm), sAl = sA + 10240, sB = sA + 20480, sBl = sA + 30720;
    int t = threadIdx.x, L = t & 31, w = t >> 5, wm = w & 1, wn = w >> 1;
    int b = blockIdx.z, n0 = blockIdx.x * 128, c0 = blockIdx.y * 128;

    float acc[4][4][4] = {};
    for (int m0 = 0; m0 < MP2_; m0 += 32) {
        int r = t >> 1, hf = t & 1;
        {   // A = attn rows n (uint4, zero-padded cols)
            int n = n0 + r;
            unsigned off = r * 80 + hf * 32;
            if (n < N_) {
                size_t ai = ((size_t)b * N_ + n) * MP2_ + m0 + hf * 16;
                *(uint4*)(sm + off)              = *(const uint4*)(g_AHi + ai);
                *(uint4*)(sm + off + 16)         = *(const uint4*)(g_AHi + ai + 8);
                *(uint4*)(sm + 10240 + off)      = *(const uint4*)(g_ALo + ai);
                *(uint4*)(sm + 10240 + off + 16) = *(const uint4*)(g_ALo + ai + 8);
            } else {
                uint4 z = make_uint4(0, 0, 0, 0);
                *(uint4*)(sm + off) = z; *(uint4*)(sm + off + 16) = z;
                *(uint4*)(sm + 10240 + off) = z; *(uint4*)(sm + 10240 + off + 16) = z;
            }
        }
        {   // B = x rows c (scalar guarded loads)
            const float* xp = x + ((size_t)b * C_ + c0 + r) * N_ + m0 + hf * 16;
            unsigned hi[8], lo[8];
            #pragma unroll
            for (int j = 0; j < 8; j++) {
                int m1 = m0 + hf * 16 + 2 * j;
                float f0 = (m1     < N_) ? __ldg(xp + 2*j)     : 0.f;
                float f1 = (m1 + 1 < N_) ? __ldg(xp + 2*j + 1) : 0.f;
                split_pack(f0, f1, hi[j], lo[j]);
            }
            unsigned off = 20480 + r * 80 + hf * 32;
            *(uint4*)(sm + off)              = ((uint4*)hi)[0];
            *(uint4*)(sm + off + 16)         = ((uint4*)hi)[1];
            *(uint4*)(sm + 10240 + off)      = ((uint4*)lo)[0];
            *(uint4*)(sm + 10240 + off + 16) = ((uint4*)lo)[1];
        }
        __syncthreads();
        gemm_chunk<0, 0>(acc, sA, sAl, sB, sBl, wm, wn, L);
        __syncthreads();
    }

    float gam = __ldg(gamma);
    float* stage = (float*)sm;
    #pragma unroll 1
    for (int ch = 0; ch < 2; ch++) {
        if ((wn >> 1) == ch) {
            #pragma unroll
            for (int fm = 0; fm < 4; fm++)
                #pragma unroll
                for (int fn = 0; fn < 4; fn++)
                    #pragma unroll
                    for (int e = 0; e < 4; e++) {
                        int cl = (wn & 1) * 32 + fn * 8 + 2 * (L & 3) + (e & 1);
                        int nl = wm * 64 + fm * 16 + (L >> 2) + (e >> 1) * 8;
                        stage[cl * 132 + nl] = acc[fm][fn][e];
                    }
        }
        __syncthreads();
        #pragma unroll 1
        for (int rr = 0; rr < 8; rr++) {
            int cc = w * 8 + rr;
            int c = c0 + ch * 64 + cc;
            size_t ob = ((size_t)b * C_ + c) * N_;
            #pragma unroll
            for (int jj = 0; jj < 4; jj++) {
                int n = n0 + jj * 32 + L;
                if (n < N_)
                    out[ob + n] = gam * stage[cc * 132 + jj * 32 + L] + __ldg(x + ob + n);
            }
        }
        __syncthreads();
    }
}

// ============================================================
extern "C" void kernel_launch(void* const* d_in, const int* in_sizes, int n_in,
                              void* d_out, int out_size)
{
    const float* x     = (const float*)d_in[0];
    const float* fg    = (const float*)d_in[1];
    const float* bg    = (const float*)d_in[2];
    const float* Wq    = (const float*)d_in[3];
    const float* bq    = (const float*)d_in[4];
    const float* Wk    = (const float*)d_in[5];
    const float* bk    = (const float*)d_in[6];
    const float* gamma = (const float*)d_in[7];
    float* out = (float*)d_out;

    proj_t<<<dim3(14, 2, 32), 256>>>(x, Wq, bq, Wk, bk);
    sim_t<<<dim3(14, 14, 16), 256>>>(fg);
    fin_stats<<<(B_ * N_ + 255) / 256, 256>>>();
    xform<<<B_ * N_, 256>>>(fg, bg);
    ctx_t<<<dim3(14, 4, 16), 256>>>(x, gamma, out);
}